// round 9
// baseline (speedup 1.0000x reference)
#include <cuda_runtime.h>
#include <cstdint>

// DQ_Add_LayerNorm_Q : fused dequant + residual add + LayerNorm + int8 requant
// rows = 16384, dim = 4096. One block per row, single DRAM pass.
// R9 = R2/R7 structure with Blackwell 256-bit vector memory ops (ld/st.global.v8):
// half the memory instructions / L1tex wavefronts per byte on every bulk stream.

constexpr int TOKENS = 16384;
constexpr int DIM = 4096;
constexpr float EPS = 1e-5f;
constexpr float INPUT_SCALE = 0.01f;

constexpr int THREADS = 256;
constexpr int VEC8 = 8;                              // 8 floats = 256-bit
constexpr int ITER = DIM / (THREADS * VEC8);         // 2 iterations per thread
constexpr int NWARP = THREADS / 32;

// ---- 256-bit global memory helpers (sm_100+) ----
__device__ __forceinline__ void ldg256_cs_f(float r[8], const float* p) {
    asm volatile("ld.global.cs.v8.f32 {%0,%1,%2,%3,%4,%5,%6,%7}, [%8];"
        : "=f"(r[0]), "=f"(r[1]), "=f"(r[2]), "=f"(r[3]),
          "=f"(r[4]), "=f"(r[5]), "=f"(r[6]), "=f"(r[7])
        : "l"(p));
}
__device__ __forceinline__ void ldg256_cs_i(int r[8], const int* p) {
    asm volatile("ld.global.cs.v8.b32 {%0,%1,%2,%3,%4,%5,%6,%7}, [%8];"
        : "=r"(r[0]), "=r"(r[1]), "=r"(r[2]), "=r"(r[3]),
          "=r"(r[4]), "=r"(r[5]), "=r"(r[6]), "=r"(r[7])
        : "l"(p));
}
__device__ __forceinline__ void ldg256_nc_f(float r[8], const float* p) {
    asm volatile("ld.global.nc.v8.f32 {%0,%1,%2,%3,%4,%5,%6,%7}, [%8];"
        : "=f"(r[0]), "=f"(r[1]), "=f"(r[2]), "=f"(r[3]),
          "=f"(r[4]), "=f"(r[5]), "=f"(r[6]), "=f"(r[7])
        : "l"(p));
}
__device__ __forceinline__ void stg256_cs_f(float* p, const float r[8]) {
    asm volatile("st.global.cs.v8.f32 [%0], {%1,%2,%3,%4,%5,%6,%7,%8};"
        :: "l"(p),
           "f"(r[0]), "f"(r[1]), "f"(r[2]), "f"(r[3]),
           "f"(r[4]), "f"(r[5]), "f"(r[6]), "f"(r[7])
        : "memory");
}

__device__ __forceinline__ float warp_sum(float v) {
#pragma unroll
    for (int off = 16; off > 0; off >>= 1)
        v += __shfl_xor_sync(0xFFFFFFFFu, v, off);
    return v;
}

template <bool Q_AS_FLOAT>
__global__ __launch_bounds__(THREADS, 4)
void fused_dq_ln_q_kernel(const float* __restrict__ resid,
                          const int*   __restrict__ qin,
                          const float* __restrict__ weight,
                          const float* __restrict__ bias,
                          float* __restrict__ xout,
                          void*  __restrict__ qout)
{
    const int row = blockIdx.x;
    const int tid = threadIdx.x;
    const size_t base = (size_t)row * DIM;

    const float* rbase = resid + base;
    const int*   qbase = qin + base;

    // Front-batch all 4 independent 256-bit loads (128B per thread in flight).
    float xv[ITER][8];
    int   qb[ITER][8];
#pragma unroll
    for (int i = 0; i < ITER; i++) {
        const int off = (tid + i * THREADS) * VEC8;
        ldg256_cs_f(xv[i], rbase + off);
        ldg256_cs_i(qb[i], qbase + off);
    }

    float s = 0.0f, ss = 0.0f;
#pragma unroll
    for (int i = 0; i < ITER; i++) {
#pragma unroll
        for (int j = 0; j < 8; j++) {
            float v = fmaf((float)qb[i][j], INPUT_SCALE, xv[i][j]);
            xv[i][j] = v;
            s  += v;
            ss = fmaf(v, v, ss);
        }
    }

    // Write updated residual x immediately (fire-and-forget, overlaps reduction).
    float* xo = xout + base;
#pragma unroll
    for (int i = 0; i < ITER; i++)
        stg256_cs_f(xo + (tid + i * THREADS) * VEC8, xv[i]);

    // block reduction of s, ss
    __shared__ float sh_s[NWARP], sh_ss[NWARP];
    float ws  = warp_sum(s);
    float wss = warp_sum(ss);
    const int lane = tid & 31, wid = tid >> 5;
    if (lane == 0) { sh_s[wid] = ws; sh_ss[wid] = wss; }
    __syncthreads();
    if (wid == 0) {
        float a = (lane < NWARP) ? sh_s[lane]  : 0.0f;
        float b = (lane < NWARP) ? sh_ss[lane] : 0.0f;
#pragma unroll
        for (int off = NWARP / 2; off > 0; off >>= 1) {
            a += __shfl_xor_sync(0xFFFFFFFFu, a, off);
            b += __shfl_xor_sync(0xFFFFFFFFu, b, off);
        }
        if (lane == 0) { sh_s[0] = a; sh_ss[0] = b; }
    }
    __syncthreads();
    const float ts = sh_s[0], tss = sh_ss[0];

    const float mean = ts * (1.0f / DIM);
    const float var  = fmaf(-mean, mean, tss * (1.0f / DIM));
    const float inv  = rsqrtf(var + EPS);

    // affine + quantize
#pragma unroll
    for (int i = 0; i < ITER; i++) {
        const int off = (tid + i * THREADS) * VEC8;
        float w[8], bb[8], qf[8];
        ldg256_nc_f(w,  weight + off);   // reused across all rows: keep cached
        ldg256_nc_f(bb, bias + off);
#pragma unroll
        for (int j = 0; j < 8; j++) {
            float l = fmaf((xv[i][j] - mean) * inv, w[j], bb[j]);
            // jnp.round = round-half-to-even -> rintf, then clip
            qf[j] = fminf(fmaxf(rintf(l), -128.0f), 127.0f);
        }
        if (Q_AS_FLOAT) {
            stg256_cs_f((float*)qout + base + off, qf);
        } else {
            int8_t* qo = (int8_t*)qout + base + off;
            uint32_t p0 = 0, p1 = 0;
#pragma unroll
            for (int j = 0; j < 4; j++) {
                p0 |= (uint32_t)((uint8_t)(int8_t)(int)qf[j])     << (8 * j);
                p1 |= (uint32_t)((uint8_t)(int8_t)(int)qf[4 + j]) << (8 * j);
            }
            uint2 pk = make_uint2(p0, p1);
            *reinterpret_cast<uint2*>(qo) = pk;
        }
    }
}

extern "C" void kernel_launch(void* const* d_in, const int* in_sizes, int n_in,
                              void* d_out, int out_size) {
    const float* resid  = (const float*)d_in[0];
    const int*   qin    = (const int*)d_in[1];
    const float* weight = (const float*)d_in[2];
    const float* bias   = (const float*)d_in[3];

    const size_t N = (size_t)TOKENS * DIM;
    float* xout = (float*)d_out;

    if ((size_t)out_size == 2 * N) {
        // outputs concatenated as float32: [x fp32 | q cast to fp32]
        void* qout = (void*)(xout + N);
        fused_dq_ln_q_kernel<true><<<TOKENS, THREADS>>>(resid, qin, weight, bias, xout, qout);
    } else {
        // byte layout: [x fp32 bytes | q int8 bytes]
        void* qout = (void*)((int8_t*)d_out + N * sizeof(float));
        fused_dq_ln_q_kernel<false><<<TOKENS, THREADS>>>(resid, qin, weight, bias, xout, qout);
    }
}

// round 11
// speedup vs baseline: 1.0002x; 1.0002x over previous
#include <cuda_runtime.h>
#include <cstdint>

// DQ_Add_LayerNorm_Q : fused dequant + residual add + LayerNorm + int8 requant
// rows = 16384, dim = 4096. One block per row, single DRAM pass.
// R10 = best-of (R2 structure, R7 register form) + x-stores folded into the
// accumulate loop so writes inject into DRAM as soon as each vector is ready,
// smoothing the per-CTA read->write burst profile.

constexpr int TOKENS = 16384;
constexpr int DIM = 4096;
constexpr float EPS = 1e-5f;
constexpr float INPUT_SCALE = 0.01f;

constexpr int THREADS = 256;
constexpr int VEC = 4;                              // float4 / int4
constexpr int ITER = DIM / (THREADS * VEC);         // 4 iterations per thread
constexpr int NWARP = THREADS / 32;

__device__ __forceinline__ float warp_sum(float v) {
#pragma unroll
    for (int off = 16; off > 0; off >>= 1)
        v += __shfl_xor_sync(0xFFFFFFFFu, v, off);
    return v;
}

template <bool Q_AS_FLOAT>
__global__ __launch_bounds__(THREADS, 5)
void fused_dq_ln_q_kernel(const float* __restrict__ resid,
                          const int*   __restrict__ qin,
                          const float* __restrict__ weight,
                          const float* __restrict__ bias,
                          float* __restrict__ xout,
                          void*  __restrict__ qout)
{
    const int row = blockIdx.x;
    const int tid = threadIdx.x;
    const size_t base = (size_t)row * DIM;

    const float4* r4 = reinterpret_cast<const float4*>(resid + base);
    const int4*   q4 = reinterpret_cast<const int4*>(qin + base);

    // Front-batch all 8 independent 128-bit loads; resid lands directly in xv.
    float4 xv[ITER];
    int4   qv[ITER];
#pragma unroll
    for (int i = 0; i < ITER; i++) {
        const int idx = tid + i * THREADS;
        xv[i] = __ldcs(&r4[idx]);   // streaming: no reuse
        qv[i] = __ldcs(&q4[idx]);
    }

    float4* xo4 = reinterpret_cast<float4*>(xout + base);

    float s = 0.0f, ss = 0.0f;
#pragma unroll
    for (int i = 0; i < ITER; i++) {
        // dequant + add in place; store x the moment this vector is ready so
        // write traffic starts flowing while later loads are still landing.
        xv[i].x = fmaf((float)qv[i].x, INPUT_SCALE, xv[i].x);
        xv[i].y = fmaf((float)qv[i].y, INPUT_SCALE, xv[i].y);
        xv[i].z = fmaf((float)qv[i].z, INPUT_SCALE, xv[i].z);
        xv[i].w = fmaf((float)qv[i].w, INPUT_SCALE, xv[i].w);
        __stcs(&xo4[tid + i * THREADS], xv[i]);
        s  += (xv[i].x + xv[i].y) + (xv[i].z + xv[i].w);
        ss += fmaf(xv[i].x, xv[i].x, xv[i].y * xv[i].y)
            + fmaf(xv[i].z, xv[i].z, xv[i].w * xv[i].w);
    }

    // block reduction of s, ss
    __shared__ float sh_s[NWARP], sh_ss[NWARP];
    float ws  = warp_sum(s);
    float wss = warp_sum(ss);
    const int lane = tid & 31, wid = tid >> 5;
    if (lane == 0) { sh_s[wid] = ws; sh_ss[wid] = wss; }
    __syncthreads();
    if (wid == 0) {
        float a = (lane < NWARP) ? sh_s[lane]  : 0.0f;
        float b = (lane < NWARP) ? sh_ss[lane] : 0.0f;
#pragma unroll
        for (int off = NWARP / 2; off > 0; off >>= 1) {
            a += __shfl_xor_sync(0xFFFFFFFFu, a, off);
            b += __shfl_xor_sync(0xFFFFFFFFu, b, off);
        }
        if (lane == 0) { sh_s[0] = a; sh_ss[0] = b; }
    }
    __syncthreads();
    const float ts = sh_s[0], tss = sh_ss[0];

    const float mean = ts * (1.0f / DIM);
    const float var  = fmaf(-mean, mean, tss * (1.0f / DIM));
    const float inv  = rsqrtf(var + EPS);

    // affine + quantize
    const float4* w4 = reinterpret_cast<const float4*>(weight);
    const float4* b4 = reinterpret_cast<const float4*>(bias);
#pragma unroll
    for (int i = 0; i < ITER; i++) {
        const int idx = tid + i * THREADS;
        float4 w  = __ldg(&w4[idx]);   // reused across all rows: keep cached
        float4 bb = __ldg(&b4[idx]);
        float4 v = xv[i];
        float lx = fmaf((v.x - mean) * inv, w.x, bb.x);
        float ly = fmaf((v.y - mean) * inv, w.y, bb.y);
        float lz = fmaf((v.z - mean) * inv, w.z, bb.z);
        float lw = fmaf((v.w - mean) * inv, w.w, bb.w);
        // jnp.round = round-half-to-even -> rintf, then clip
        float qx = fminf(fmaxf(rintf(lx), -128.0f), 127.0f);
        float qy = fminf(fmaxf(rintf(ly), -128.0f), 127.0f);
        float qz = fminf(fmaxf(rintf(lz), -128.0f), 127.0f);
        float qw = fminf(fmaxf(rintf(lw), -128.0f), 127.0f);
        if (Q_AS_FLOAT) {
            float4* qo = reinterpret_cast<float4*>((float*)qout + base);
            __stcs(&qo[idx], make_float4(qx, qy, qz, qw));
        } else {
            char4* qo = reinterpret_cast<char4*>((int8_t*)qout + base);
            char4 c;
            c.x = (signed char)(int)qx;
            c.y = (signed char)(int)qy;
            c.z = (signed char)(int)qz;
            c.w = (signed char)(int)qw;
            qo[idx] = c;
        }
    }
}

extern "C" void kernel_launch(void* const* d_in, const int* in_sizes, int n_in,
                              void* d_out, int out_size) {
    const float* resid  = (const float*)d_in[0];
    const int*   qin    = (const int*)d_in[1];
    const float* weight = (const float*)d_in[2];
    const float* bias   = (const float*)d_in[3];

    const size_t N = (size_t)TOKENS * DIM;
    float* xout = (float*)d_out;

    if ((size_t)out_size == 2 * N) {
        // outputs concatenated as float32: [x fp32 | q cast to fp32]
        void* qout = (void*)(xout + N);
        fused_dq_ln_q_kernel<true><<<TOKENS, THREADS>>>(resid, qin, weight, bias, xout, qout);
    } else {
        // byte layout: [x fp32 bytes | q int8 bytes]
        void* qout = (void*)((int8_t*)d_out + N * sizeof(float));
        fused_dq_ln_q_kernel<false><<<TOKENS, THREADS>>>(resid, qin, weight, bias, xout, qout);
    }
}